// round 1
// baseline (speedup 1.0000x reference)
#include <cuda_runtime.h>
#include <cuda_bf16.h>

// Problem constants
#define H   1024
#define B   64
#define S   512
#define W3H 3072   // W row stride (3*H)

// Scratch (no device allocation allowed)
__device__ float g_u2[H];          // u2 = W[:, 2H:3H]^T v
__device__ float g_scores[B * S];  // pre-softmax scores

// ---------------------------------------------------------------------------
// Kernel 1: u2[k] = sum_h v[h] * W[h, 2H + k]
// grid = 32 blocks, 256 threads (8 h-slices x 32 k-lanes). Coalesced over k.
// ---------------------------------------------------------------------------
__global__ void k_u2(const float* __restrict__ W, const float* __restrict__ v) {
    const int tx = threadIdx.x & 31;   // k lane
    const int ty = threadIdx.x >> 5;   // h slice (0..7)
    const int k  = blockIdx.x * 32 + tx;

    float acc = 0.f;
#pragma unroll 4
    for (int h = ty; h < H; h += 8) {
        acc += v[h] * __ldg(&W[(size_t)h * W3H + 2 * H + k]);
    }

    __shared__ float sm[8][33];
    sm[ty][tx] = acc;
    __syncthreads();
    if (ty == 0) {
        float s = 0.f;
#pragma unroll
        for (int j = 0; j < 8; j++) s += sm[j][tx];
        g_u2[k] = s;
    }
}

// ---------------------------------------------------------------------------
// Kernel 2: scores[row] = enc[row, :] . u2      (row = b*S + s, 32768 rows)
// One warp per row. Each lane: 8x float4 (32 floats). Fully coalesced, MLP=8.
// ---------------------------------------------------------------------------
__global__ void k_scores(const float4* __restrict__ enc) {
    const int warp = (blockIdx.x * blockDim.x + threadIdx.x) >> 5;
    const int lane = threadIdx.x & 31;

    const float4* __restrict__ row = enc + (size_t)warp * (H / 4);
    const float4* __restrict__ u   = (const float4*)g_u2;

    float acc = 0.f;
#pragma unroll
    for (int j = 0; j < 8; j++) {
        const float4 e = __ldg(&row[lane + j * 32]);
        const float4 w = u[lane + j * 32];
        acc += e.x * w.x + e.y * w.y + e.z * w.z + e.w * w.w;
    }

#pragma unroll
    for (int off = 16; off > 0; off >>= 1)
        acc += __shfl_xor_sync(0xffffffffu, acc, off);

    if (lane == 0) g_scores[warp] = acc;
}

// ---------------------------------------------------------------------------
// Kernel 3: per-b softmax over 512 scores. One block of 256 threads per b.
// ---------------------------------------------------------------------------
__global__ void k_softmax(float* __restrict__ out) {
    const int b   = blockIdx.x;
    const int tid = threadIdx.x;  // 256
    const float* sc = g_scores + b * S;

    const float v0 = sc[tid];
    const float v1 = sc[tid + 256];

    __shared__ float sm[256];
    sm[tid] = fmaxf(v0, v1);
    __syncthreads();
#pragma unroll
    for (int st = 128; st > 0; st >>= 1) {
        if (tid < st) sm[tid] = fmaxf(sm[tid], sm[tid + st]);
        __syncthreads();
    }
    const float mx = sm[0];
    __syncthreads();

    const float e0 = __expf(v0 - mx);
    const float e1 = __expf(v1 - mx);
    sm[tid] = e0 + e1;
    __syncthreads();
#pragma unroll
    for (int st = 128; st > 0; st >>= 1) {
        if (tid < st) sm[tid] += sm[tid + st];
        __syncthreads();
    }
    const float inv = 1.f / sm[0];

    out[b * S + tid]       = e0 * inv;
    out[b * S + tid + 256] = e1 * inv;
}

// ---------------------------------------------------------------------------
// Inputs (metadata order): hidden[2,B,H], encoder_outputs[B,S,H],
//                          W[H,3H], b[H], v[H]
// hidden and b are mathematically irrelevant post-softmax (per-row constants).
// ---------------------------------------------------------------------------
extern "C" void kernel_launch(void* const* d_in, const int* in_sizes, int n_in,
                              void* d_out, int out_size) {
    const float* enc = (const float*)d_in[1];
    const float* W   = (const float*)d_in[2];
    const float* v   = (const float*)d_in[4];
    float* out = (float*)d_out;

    k_u2<<<H / 32, 256>>>(W, v);
    k_scores<<<(B * S) / 8, 256>>>((const float4*)enc);
    k_softmax<<<B, 256>>>(out);
}

// round 2
// speedup vs baseline: 1.4241x; 1.4241x over previous
#include <cuda_runtime.h>
#include <cuda_bf16.h>

// Problem constants
#define H   1024
#define B   64
#define S   512
#define W3H 3072   // W row stride (3*H)

// Scratch (no device allocation allowed)
__device__ float g_u2[H];          // u2 = W[:, 2H:3H]^T v
__device__ float g_scores[B * S];  // pre-softmax scores

// ---------------------------------------------------------------------------
// Kernel 0: zero the u2 accumulator (atomicAdd target).
// ---------------------------------------------------------------------------
__global__ void k_zero() {
    g_u2[threadIdx.x] = 0.f;
}

// ---------------------------------------------------------------------------
// Kernel 1: u2[k] = sum_h v[h] * W[h, 2H + k]
// grid = (4, 32): x tiles k (256 floats = 64 float4 per block),
//                 y tiles h (32 rows per block).
// 256 threads: tx = t&63 -> k float4 lane, ty = t>>6 -> h slice (0..3).
// Each thread: 8 float4 loads (MLP=8), partials combined via shared +
// atomicAdd (distinct addresses -> RED, cheap). 128 blocks -> chip-wide MLP.
// ---------------------------------------------------------------------------
__global__ void k_u2(const float* __restrict__ W, const float* __restrict__ v) {
    const int tx = threadIdx.x & 63;   // k-float4 lane within block tile
    const int ty = threadIdx.x >> 6;   // h slice (0..3)
    const int k4 = blockIdx.x * 64 + tx;        // float4 index into 1024-k slice
    const int h0 = blockIdx.y * 32 + ty;        // starting h row

    float4 acc = make_float4(0.f, 0.f, 0.f, 0.f);
#pragma unroll
    for (int j = 0; j < 8; j++) {
        const int h = h0 + j * 4;
        const float vh = v[h];
        const float4 w = __ldg((const float4*)(W + (size_t)h * W3H + 2 * H) + k4);
        acc.x += vh * w.x;
        acc.y += vh * w.y;
        acc.z += vh * w.z;
        acc.w += vh * w.w;
    }

    __shared__ float4 sm[4][64];
    sm[ty][tx] = acc;
    __syncthreads();
    if (ty == 0) {
        float4 s = sm[0][tx];
#pragma unroll
        for (int j = 1; j < 4; j++) {
            const float4 p = sm[j][tx];
            s.x += p.x; s.y += p.y; s.z += p.z; s.w += p.w;
        }
        float* dst = g_u2 + k4 * 4;
        atomicAdd(dst + 0, s.x);
        atomicAdd(dst + 1, s.y);
        atomicAdd(dst + 2, s.z);
        atomicAdd(dst + 3, s.w);
    }
}

// ---------------------------------------------------------------------------
// Kernel 2: scores[row] = enc[row, :] . u2      (row = b*S + s, 32768 rows)
// One warp per row. Each lane: 8x float4 (32 floats). Fully coalesced, MLP=8.
// ---------------------------------------------------------------------------
__global__ void k_scores(const float4* __restrict__ enc) {
    const int warp = (blockIdx.x * blockDim.x + threadIdx.x) >> 5;
    const int lane = threadIdx.x & 31;

    const float4* __restrict__ row = enc + (size_t)warp * (H / 4);
    const float4* __restrict__ u   = (const float4*)g_u2;

    float acc = 0.f;
#pragma unroll
    for (int j = 0; j < 8; j++) {
        const float4 e = __ldg(&row[lane + j * 32]);
        const float4 w = u[lane + j * 32];
        acc += e.x * w.x + e.y * w.y + e.z * w.z + e.w * w.w;
    }

#pragma unroll
    for (int off = 16; off > 0; off >>= 1)
        acc += __shfl_xor_sync(0xffffffffu, acc, off);

    if (lane == 0) g_scores[warp] = acc;
}

// ---------------------------------------------------------------------------
// Kernel 3: per-b softmax over 512 scores. One block of 256 threads per b.
// ---------------------------------------------------------------------------
__global__ void k_softmax(float* __restrict__ out) {
    const int b   = blockIdx.x;
    const int tid = threadIdx.x;  // 256
    const float* sc = g_scores + b * S;

    const float v0 = sc[tid];
    const float v1 = sc[tid + 256];

    __shared__ float sm[256];
    sm[tid] = fmaxf(v0, v1);
    __syncthreads();
#pragma unroll
    for (int st = 128; st > 0; st >>= 1) {
        if (tid < st) sm[tid] = fmaxf(sm[tid], sm[tid + st]);
        __syncthreads();
    }
    const float mx = sm[0];
    __syncthreads();

    const float e0 = __expf(v0 - mx);
    const float e1 = __expf(v1 - mx);
    sm[tid] = e0 + e1;
    __syncthreads();
#pragma unroll
    for (int st = 128; st > 0; st >>= 1) {
        if (tid < st) sm[tid] += sm[tid + st];
        __syncthreads();
    }
    const float inv = 1.f / sm[0];

    out[b * S + tid]       = e0 * inv;
    out[b * S + tid + 256] = e1 * inv;
}

// ---------------------------------------------------------------------------
// Inputs (metadata order): hidden[2,B,H], encoder_outputs[B,S,H],
//                          W[H,3H], b[H], v[H]
// hidden and b are mathematically irrelevant post-softmax (per-row constants).
// ---------------------------------------------------------------------------
extern "C" void kernel_launch(void* const* d_in, const int* in_sizes, int n_in,
                              void* d_out, int out_size) {
    const float* enc = (const float*)d_in[1];
    const float* W   = (const float*)d_in[2];
    const float* v   = (const float*)d_in[4];
    float* out = (float*)d_out;

    k_zero<<<1, H>>>();
    {
        dim3 grid(4, 32);
        k_u2<<<grid, 256>>>(W, v);
    }
    k_scores<<<(B * S) / 8, 256>>>((const float4*)enc);
    k_softmax<<<B, 256>>>(out);
}

// round 3
// speedup vs baseline: 1.4337x; 1.0067x over previous
#include <cuda_runtime.h>
#include <cuda_bf16.h>

// Problem constants
#define H   1024
#define B   64
#define S   512
#define W3H 3072            // W row stride (3*H)
#define BLKS_PER_B 64       // fused kernel: blocks per batch row (8 rows each)

// Scratch (zero-initialized at module load; every launch leaves it zeroed again,
// so each graph replay is deterministic).
__device__ float g_u2[H];            // u2 = W[:, 2H:3H]^T v   (accumulated, then reset)
__device__ float g_scores[B * S];    // pre-softmax scores
__device__ int   g_cnt[B];           // per-b completion counters (reset by last block)
__device__ int   g_gcnt;             // global completion counter (reset by last)

// ---------------------------------------------------------------------------
// Kernel 1: u2[k] += sum_h v[h] * W[h, 2H + k]       (g_u2 pre-zeroed)
// grid = (4, 32): x tiles k, y tiles h. atomicAdd partials (distinct addrs).
// ---------------------------------------------------------------------------
__global__ void k_u2(const float* __restrict__ W, const float* __restrict__ v) {
    const int tx = threadIdx.x & 63;   // k-float4 lane within block tile
    const int ty = threadIdx.x >> 6;   // h slice (0..3)
    const int k4 = blockIdx.x * 64 + tx;
    const int h0 = blockIdx.y * 32 + ty;

    float4 acc = make_float4(0.f, 0.f, 0.f, 0.f);
#pragma unroll
    for (int j = 0; j < 8; j++) {
        const int h = h0 + j * 4;
        const float vh = v[h];
        const float4 w = __ldg((const float4*)(W + (size_t)h * W3H + 2 * H) + k4);
        acc.x += vh * w.x;
        acc.y += vh * w.y;
        acc.z += vh * w.z;
        acc.w += vh * w.w;
    }

    __shared__ float4 sm[4][64];
    sm[ty][tx] = acc;
    __syncthreads();
    if (ty == 0) {
        float4 s = sm[0][tx];
#pragma unroll
        for (int j = 1; j < 4; j++) {
            const float4 p = sm[j][tx];
            s.x += p.x; s.y += p.y; s.z += p.z; s.w += p.w;
        }
        float* dst = g_u2 + k4 * 4;
        atomicAdd(dst + 0, s.x);
        atomicAdd(dst + 1, s.y);
        atomicAdd(dst + 2, s.z);
        atomicAdd(dst + 3, s.w);
    }
}

// ---------------------------------------------------------------------------
// Kernel 2 (fused): scores + per-b softmax + self-clean.
// grid = B * BLKS_PER_B = 4096 blocks, 256 threads (8 warps -> 8 rows).
// Block bx: b = bx/64, rows s = (bx%64)*8 + warp.
// Last block per b (atomic ticket) re-reads the 512 scores and softmaxes.
// Globally-last block re-zeroes g_u2 and g_gcnt for the next launch.
// ---------------------------------------------------------------------------
__global__ void k_fused(const float4* __restrict__ enc, float* __restrict__ out) {
    const int b     = blockIdx.x >> 6;
    const int chunk = blockIdx.x & 63;
    const int warp  = threadIdx.x >> 5;
    const int lane  = threadIdx.x & 31;
    const int row   = b * S + chunk * 8 + warp;   // global row in [0, B*S)

    const float4* __restrict__ rp = enc + (size_t)row * (H / 4);
    const float4* __restrict__ u  = (const float4*)g_u2;

    float acc = 0.f;
#pragma unroll
    for (int j = 0; j < 8; j++) {
        const float4 e = __ldcs(&rp[lane + j * 32]);   // streaming, evict-first
        const float4 w = u[lane + j * 32];
        acc += e.x * w.x + e.y * w.y + e.z * w.z + e.w * w.w;
    }
#pragma unroll
    for (int off = 16; off > 0; off >>= 1)
        acc += __shfl_xor_sync(0xffffffffu, acc, off);
    if (lane == 0) g_scores[row] = acc;

    // --- last-block-per-b does the softmax ---
    __shared__ int s_ticket;
    __threadfence();                     // make score writes visible chip-wide
    __syncthreads();                     // all warps of this block done
    if (threadIdx.x == 0)
        s_ticket = atomicAdd(&g_cnt[b], 1);
    __syncthreads();

    if (s_ticket == BLKS_PER_B - 1) {
        const int tid = threadIdx.x;     // 256
        const float* sc = g_scores + b * S;
        const float v0 = __ldcg(&sc[tid]);
        const float v1 = __ldcg(&sc[tid + 256]);

        __shared__ float sm[256];
        sm[tid] = fmaxf(v0, v1);
        __syncthreads();
#pragma unroll
        for (int st = 128; st > 0; st >>= 1) {
            if (tid < st) sm[tid] = fmaxf(sm[tid], sm[tid + st]);
            __syncthreads();
        }
        const float mx = sm[0];
        __syncthreads();

        const float e0 = __expf(v0 - mx);
        const float e1 = __expf(v1 - mx);
        sm[tid] = e0 + e1;
        __syncthreads();
#pragma unroll
        for (int st = 128; st > 0; st >>= 1) {
            if (tid < st) sm[tid] += sm[tid + st];
            __syncthreads();
        }
        const float inv = 1.f / sm[0];

        out[b * S + tid]       = e0 * inv;
        out[b * S + tid + 256] = e1 * inv;

        // --- self-clean for the next launch ---
        if (tid == 0) {
            g_cnt[b] = 0;
            __threadfence();
            const int g = atomicAdd(&g_gcnt, 1);
            s_ticket = (g == B - 1) ? 1 : 0;
        }
        __syncthreads();
        if (s_ticket == 1) {
            // globally last block: zero u2 and the global counter
            ((float4*)g_u2)[tid] = make_float4(0.f, 0.f, 0.f, 0.f);
            if (tid == 0) g_gcnt = 0;
        }
    }
}

// ---------------------------------------------------------------------------
// Inputs (metadata order): hidden[2,B,H], encoder_outputs[B,S,H],
//                          W[H,3H], b[H], v[H]
// hidden and b are mathematically irrelevant post-softmax (per-row constants).
// ---------------------------------------------------------------------------
extern "C" void kernel_launch(void* const* d_in, const int* in_sizes, int n_in,
                              void* d_out, int out_size) {
    const float* enc = (const float*)d_in[1];
    const float* W   = (const float*)d_in[2];
    const float* v   = (const float*)d_in[4];
    float* out = (float*)d_out;

    {
        dim3 grid(4, 32);
        k_u2<<<grid, 256>>>(W, v);
    }
    k_fused<<<B * BLKS_PER_B, 256>>>((const float4*)enc, out);
}